// round 4
// baseline (speedup 1.0000x reference)
#include <cuda_runtime.h>
#include <math.h>
#include <stdint.h>

#define VOCAB    128000
#define NSEQ     256
#define TOPK     50
#define NTHREADS 1024
#define NBINS    8192
#define CAP      1024
#define NV4      (VOCAB / 4)

// per-vocab penalty table: bits[0:16)=output count, bit16=prompt flag, bit17=eos flag
__device__ unsigned g_table[VOCAB];

__global__ void k_zero_table() {
  int i = blockIdx.x * blockDim.x + threadIdx.x;
  if (i < VOCAB) g_table[i] = 0u;
}

__global__ void k_scatter(const int* __restrict__ prompt, int np,
                          const int* __restrict__ outtok, int no,
                          const int* __restrict__ eos, int ne) {
  int tid = threadIdx.x;
  for (int i = tid; i < np; i += blockDim.x) atomicOr(&g_table[prompt[i]], 1u << 16);
  for (int i = tid; i < no; i += blockDim.x) atomicAdd(&g_table[outtok[i]], 1u);
  for (int i = tid; i < ne; i += blockDim.x) atomicOr(&g_table[eos[i]], 1u << 17);
}

// Bit-faithful to the reference float path: every op rounded separately (no FFMA).
__device__ __forceinline__ float adjust_logit(float x, unsigned e) {
  if (e & (1u << 17)) return -INFINITY;                    // eos mask
  int cnt = (int)(e & 0xFFFFu);
  float rep = (e & 0x1FFFFu) ? 1.1f : 1.0f;                // prompt|output mask
  float y = (x > 0.0f) ? __fdiv_rn(x, rep) : __fmul_rn(x, rep);
  y = __fsub_rn(y, __fmul_rn(0.1f, (float)cnt));           // frequency
  if (cnt > 0) y = __fsub_rn(y, 0.2f);                     // presence
  y = __fdiv_rn(y, 0.8f);                                  // temperature
  return y;
}

__device__ __forceinline__ unsigned orderable(float f) {
  unsigned u = __float_as_uint(f);
  return (u & 0x80000000u) ? ~u : (u | 0x80000000u);
}
__device__ __forceinline__ float inv_orderable(unsigned o) {
  return __uint_as_float((o & 0x80000000u) ? (o ^ 0x80000000u) : ~o);
}

// JAX threefry2x32, partitionable: bits = x0 ^ x1 of threefry(key=(0,1), counter=(0, n))
__device__ __forceinline__ float gumbel_at(long long n) {
  unsigned c0 = (unsigned)((unsigned long long)n >> 32);
  unsigned c1 = (unsigned)n;
  const unsigned ks0 = 0u, ks1 = 1u, ks2 = 0x1BD11BDBu;
  unsigned x0 = c0 + ks0, x1 = c1 + ks1;
#define TF_RND(r) { x0 += x1; x1 = (x1 << (r)) | (x1 >> (32 - (r))); x1 ^= x0; }
  TF_RND(13) TF_RND(15) TF_RND(26) TF_RND(6)  x0 += ks1; x1 += ks2 + 1u;
  TF_RND(17) TF_RND(29) TF_RND(16) TF_RND(24) x0 += ks2; x1 += ks0 + 2u;
  TF_RND(13) TF_RND(15) TF_RND(26) TF_RND(6)  x0 += ks0; x1 += ks1 + 3u;
  TF_RND(17) TF_RND(29) TF_RND(16) TF_RND(24) x0 += ks1; x1 += ks2 + 4u;
  TF_RND(13) TF_RND(15) TF_RND(26) TF_RND(6)  x0 += ks2; x1 += ks0 + 5u;
#undef TF_RND
  unsigned bits = x0 ^ x1;
  float f = __uint_as_float((bits >> 9) | 0x3f800000u) - 1.0f;
  float u = fmaxf(__uint_as_float(0x00800000u), f);
  return -logf(-logf(u));
}

__global__ __launch_bounds__(NTHREADS, 2)
void k_main(const float* __restrict__ logits, float* __restrict__ out,
            int prob_off, int tok_off, int tok_int) {
  __shared__ unsigned hist[NBINS];
  __shared__ unsigned partial[NTHREADS];
  __shared__ unsigned long long skey[CAP];   // (orderable(val)<<32) | vocab_idx
  __shared__ float sval[CAP];
  __shared__ int   sidx[CAP];
  __shared__ unsigned s_cnt;
  __shared__ int s_g, s_bstar, s_J;

  const int s = blockIdx.x;
  const int tid = threadIdx.x;

  for (int i = tid; i < NBINS; i += NTHREADS) hist[i] = 0u;
  if (tid == 0) { s_cnt = 0u; s_g = 0; }
  __syncthreads();

  const float4* row4 = (const float4*)(logits + (size_t)s * VOCAB);
  float4* prow4 = (prob_off >= 0) ? (float4*)(out + prob_off + (size_t)s * VOCAB) : (float4*)0;

  // ---- Pass 1: histogram of adjusted logits (top 13 orderable bits) + fused zero-fill ----
  for (int c = tid; c < NV4; c += NTHREADS) {
    float4 t = row4[c];
    if (prow4) prow4[c] = make_float4(0.f, 0.f, 0.f, 0.f);
    int vb = c * 4;
    float xs4[4] = {t.x, t.y, t.z, t.w};
#pragma unroll
    for (int q = 0; q < 4; q++) {
      unsigned e = g_table[vb + q];
      float y = adjust_logit(xs4[q], e);
      atomicAdd(&hist[orderable(y) >> 19], 1u);
    }
  }
  __syncthreads();

  // ---- Suffix-sum over 8192 bins to locate the top-k cutoff bin ----
  unsigned ps = 0u;
#pragma unroll
  for (int q = 0; q < 8; q++) ps += hist[tid * 8 + q];
  partial[tid] = ps;
  __syncthreads();
  for (int off = 1; off < NTHREADS; off <<= 1) {
    unsigned a = (tid + off < NTHREADS) ? partial[tid + off] : 0u;
    __syncthreads();
    partial[tid] += a;
    __syncthreads();
  }
  {
    unsigned sufi = partial[tid];
    unsigned sufn = (tid + 1 < NTHREADS) ? partial[tid + 1] : 0u;
    if (sufi >= TOPK && sufn < TOPK) s_g = tid;
  }
  __syncthreads();
  if (tid == 0) {
    int g = s_g;
    unsigned acc = (g + 1 < NTHREADS) ? partial[g + 1] : 0u;
    int b = g * 8;
    for (int q = 7; q >= 0; q--) {
      acc += hist[g * 8 + q];
      if (acc >= TOPK) { b = g * 8 + q; break; }
    }
    s_bstar = b;
  }
  __syncthreads();
  const unsigned bstar = (unsigned)s_bstar;

  // ---- Pass 2: collect candidates (all elements in bins >= bstar) ----
  for (int c = tid; c < NV4; c += NTHREADS) {
    float4 t = row4[c];
    int vb = c * 4;
    float xs4[4] = {t.x, t.y, t.z, t.w};
#pragma unroll
    for (int q = 0; q < 4; q++) {
      unsigned e = g_table[vb + q];
      unsigned o = orderable(adjust_logit(xs4[q], e));
      if ((o >> 19) >= bstar) {
        unsigned p = atomicAdd(&s_cnt, 1u);
        if (p < CAP) skey[p] = ((unsigned long long)o << 32) | (unsigned)(vb + q);
      }
    }
  }
  __syncthreads();
  int n = (int)s_cnt; if (n > CAP) n = CAP;
  for (int i = tid; i < CAP; i += NTHREADS)
    if (i >= n) skey[i] = 0ull;   // sorts last under descending order
  __syncthreads();

  // ---- Bitonic sort DESC on (value, vocab_idx) key: stable-tie reverse of jnp.argsort asc ----
  for (int k = 2; k <= CAP; k <<= 1) {
    for (int j = k >> 1; j > 0; j >>= 1) {
      int i = tid, l = i ^ j;
      if (l > i) {
        unsigned long long a = skey[i], b = skey[l];
        bool sw = ((i & k) == 0) ? (a < b) : (a > b);
        if (sw) { skey[i] = b; skey[l] = a; }
      }
      __syncthreads();
    }
  }

  // decode sorted keys
  for (int i = tid; i < CAP; i += NTHREADS) {
    unsigned long long kk = skey[i];
    if (i < n) { sval[i] = inv_orderable((unsigned)(kk >> 32)); sidx[i] = (int)(kk & 0xFFFFFFFFu); }
    else       { sval[i] = -INFINITY; sidx[i] = 0x7FFFFFFF; }
  }
  __syncthreads();

  // ---- Serial epilogue: tau, softmax, ascending cumsum top-p, renormalize ----
  if (tid == 0) {
    const float T = (float)(1.0 - 0.9);
    float tau = sval[TOPK - 1];
    int Kp = n;
    for (int i = TOPK; i < n; i++) if (sval[i] < tau) { Kp = i; break; }
    float m = sval[0];
    float Ssum = 0.f;
    for (int i = Kp - 1; i >= 0; i--) Ssum += expf(sval[i] - m);   // ascending order
    float c = 0.f; int J = Kp;
    for (int i = Kp - 1; i >= 0; i--) {
      c += expf(sval[i] - m) / Ssum;
      if (c > T) { J = i + 1; break; }
    }
    float Z = 0.f;
    for (int i = J - 1; i >= 0; i--) Z += expf(sval[i] - m);
    for (int i = 0; i < J; i++) sval[i] = expf(sval[i] - m) / Z;
    s_J = J;
  }
  __syncthreads();
  int J = s_J;

  if (prob_off >= 0) {
    float* prow = out + prob_off + (size_t)s * VOCAB;
    for (int i = tid; i < J; i += NTHREADS) prow[sidx[i]] = sval[i];
  }

  // ---- Gumbel-argmax sampling over the J survivors (warp 0) ----
  if (tok_off >= 0 && tid < 32) {
    float best = -INFINITY; int bidx = 0x7FFFFFFF;
    for (int i = tid; i < J; i += 32) {
      float sc = logf(sval[i]) + gumbel_at((long long)s * VOCAB + sidx[i]);
      if (sc > best || (sc == best && sidx[i] < bidx)) { best = sc; bidx = sidx[i]; }
    }
    for (int o = 16; o; o >>= 1) {
      float ob = __shfl_down_sync(0xffffffffu, best, o);
      int oi   = __shfl_down_sync(0xffffffffu, bidx, o);
      if (ob > best || (ob == best && oi < bidx)) { best = ob; bidx = oi; }
    }
    if (tid == 0) {
      if (tok_int) ((int*)out)[tok_off + s] = bidx;
      else         out[tok_off + s] = (float)bidx;
    }
  }
}

extern "C" void kernel_launch(void* const* d_in, const int* in_sizes, int n_in,
                              void* d_out, int out_size) {
  const float* logits = (const float*)d_in[0];
  const int* prompt  = (const int*)d_in[1];
  const int* outtok  = (const int*)d_in[2];
  const int* eos     = (const int*)d_in[3];
  int np = in_sizes[1], no = in_sizes[2], ne = in_sizes[3];

  k_zero_table<<<(VOCAB + 1023) / 1024, 1024>>>();
  k_scatter<<<1, 1024>>>(prompt, np, outtok, no, eos, ne);

  const long long SV = (long long)NSEQ * VOCAB;
  int prob_off, tok_off, tok_int;
  if (out_size == (int)(SV + NSEQ)) { tok_off = 0;  prob_off = NSEQ; tok_int = 0; }
  else if (out_size == (int)SV)     { tok_off = -1; prob_off = 0;    tok_int = 0; }
  else if (out_size == NSEQ)        { tok_off = 0;  prob_off = -1;   tok_int = 1; }
  else                              { tok_off = 0;  prob_off = NSEQ; tok_int = 0; }

  k_main<<<NSEQ, NTHREADS>>>(logits, (float*)d_out, prob_off, tok_off, tok_int);
}

// round 6
// speedup vs baseline: 2.1356x; 2.1356x over previous
#include <cuda_runtime.h>
#include <math.h>
#include <stdint.h>

#define VOCAB    128000
#define NSEQ     256
#define TOPK     50
#define NTHREADS 1024
#define NBINS    8192
#define CAP      1024          // candidate capacity == sort size
#define NV4      (VOCAB / 4)
#define THX      2.6f          // raw-logit prefilter
#define THY      3.25f         // = THX/0.8 : upper bound on y for non-candidates

// per-vocab penalty table: bits[0:16)=output count, bit16=prompt flag, bit17=eos flag
__device__ unsigned g_table[VOCAB];

__global__ void k_zero_table() {
  int i = blockIdx.x * blockDim.x + threadIdx.x;
  if (i < VOCAB) g_table[i] = 0u;
}

__global__ void k_scatter(const int* __restrict__ prompt, int np,
                          const int* __restrict__ outtok, int no,
                          const int* __restrict__ eos, int ne) {
  int tid = threadIdx.x;
  for (int i = tid; i < np; i += blockDim.x) atomicOr(&g_table[prompt[i]], 1u << 16);
  for (int i = tid; i < no; i += blockDim.x) atomicAdd(&g_table[outtok[i]], 1u);
  for (int i = tid; i < ne; i += blockDim.x) atomicOr(&g_table[eos[i]], 1u << 17);
}

// Bit-faithful to the reference float path: every op rounded separately (no FFMA).
__device__ __forceinline__ float adjust_logit(float x, unsigned e) {
  if (e & (1u << 17)) return -INFINITY;                    // eos mask
  int cnt = (int)(e & 0xFFFFu);
  float rep = (e & 0x1FFFFu) ? 1.1f : 1.0f;                // prompt|output mask
  float y = (x > 0.0f) ? __fdiv_rn(x, rep) : __fmul_rn(x, rep);
  y = __fsub_rn(y, __fmul_rn(0.1f, (float)cnt));           // frequency
  if (cnt > 0) y = __fsub_rn(y, 0.2f);                     // presence
  y = __fdiv_rn(y, 0.8f);                                  // temperature
  return y;
}

__device__ __forceinline__ unsigned orderable(float f) {
  unsigned u = __float_as_uint(f);
  return (u & 0x80000000u) ? ~u : (u | 0x80000000u);
}
__device__ __forceinline__ float inv_orderable(unsigned o) {
  return __uint_as_float((o & 0x80000000u) ? (o ^ 0x80000000u) : ~o);
}

// JAX threefry2x32, partitionable: bits = x0 ^ x1 of threefry(key=(0,1), counter=(0, n))
__device__ __forceinline__ float gumbel_at(long long n) {
  unsigned c0 = (unsigned)((unsigned long long)n >> 32);
  unsigned c1 = (unsigned)n;
  const unsigned ks0 = 0u, ks1 = 1u, ks2 = 0x1BD11BDBu;
  unsigned x0 = c0 + ks0, x1 = c1 + ks1;
#define TF_RND(r) { x0 += x1; x1 = (x1 << (r)) | (x1 >> (32 - (r))); x1 ^= x0; }
  TF_RND(13) TF_RND(15) TF_RND(26) TF_RND(6)  x0 += ks1; x1 += ks2 + 1u;
  TF_RND(17) TF_RND(29) TF_RND(16) TF_RND(24) x0 += ks2; x1 += ks0 + 2u;
  TF_RND(13) TF_RND(15) TF_RND(26) TF_RND(6)  x0 += ks0; x1 += ks1 + 3u;
  TF_RND(17) TF_RND(29) TF_RND(16) TF_RND(24) x0 += ks1; x1 += ks2 + 4u;
  TF_RND(13) TF_RND(15) TF_RND(26) TF_RND(6)  x0 += ks2; x1 += ks0 + 5u;
#undef TF_RND
  unsigned bits = x0 ^ x1;
  float f = __uint_as_float((bits >> 9) | 0x3f800000u) - 1.0f;
  float u = fmaxf(__uint_as_float(0x00800000u), f);
  return -logf(-logf(u));
}

// Descending bitonic sort over CAP slots, one slot per thread (NTHREADS == CAP).
__device__ __forceinline__ void bitonic_desc(unsigned long long* skey, int tid) {
  for (int k = 2; k <= CAP; k <<= 1) {
    for (int j = k >> 1; j > 0; j >>= 1) {
      int i = tid, l = i ^ j;
      if (l > i) {
        unsigned long long a = skey[i], b = skey[l];
        bool sw = ((i & k) == 0) ? (a < b) : (a > b);
        if (sw) { skey[i] = b; skey[l] = a; }
      }
      __syncthreads();
    }
  }
}

__global__ __launch_bounds__(NTHREADS, 2)
void k_main(const float* __restrict__ logits, float* __restrict__ out,
            int prob_off, int tok_off, int tok_int) {
  __shared__ unsigned hist[NBINS];          // slow path only
  __shared__ unsigned partial[NTHREADS];    // slow path only
  __shared__ unsigned long long skey[CAP];  // (orderable(y)<<32) | vocab_idx
  __shared__ float sval[CAP];
  __shared__ int   sidx[CAP];
  __shared__ unsigned s_cnt;
  __shared__ int s_g, s_bstar, s_J, s_ok;

  const int s = blockIdx.x;
  const int tid = threadIdx.x;

  if (tid == 0) { s_cnt = 0u; s_g = 0; }
  __syncthreads();

  const float4* row4 = (const float4*)(logits + (size_t)s * VOCAB);
  float4* prow4 = (prob_off >= 0) ? (float4*)(out + prob_off + (size_t)s * VOCAB) : (float4*)0;

  // ---- Single streaming pass: fused zero-fill + prefiltered candidate collection ----
  // Any element with raw x <= THX has adjusted y <= THY < tau, so it cannot reach
  // top-k (verified after sorting; guarded slow path otherwise).
#pragma unroll 2
  for (int c = tid; c < NV4; c += NTHREADS) {
    float4 t = row4[c];
    if (prow4) prow4[c] = make_float4(0.f, 0.f, 0.f, 0.f);
    if (t.x > THX || t.y > THX || t.z > THX || t.w > THX) {
      int vb = c * 4;
      float xs4[4] = {t.x, t.y, t.z, t.w};
#pragma unroll
      for (int q = 0; q < 4; q++) {
        if (xs4[q] > THX) {
          unsigned e = g_table[vb + q];
          unsigned o = orderable(adjust_logit(xs4[q], e));
          unsigned p = atomicAdd(&s_cnt, 1u);
          if (p < CAP) skey[p] = ((unsigned long long)o << 32) | (unsigned)(vb + q);
        }
      }
    }
  }
  __syncthreads();

  int n = (int)s_cnt;
  bool okn = (n >= TOPK && n <= CAP);
  if (okn) {
    for (int i = tid; i < CAP; i += NTHREADS)
      if (i >= n) skey[i] = 0ull;
    __syncthreads();
    bitonic_desc(skey, tid);                 // desc (value, idx): stable-tie reverse of asc argsort
    for (int i = tid; i < CAP; i += NTHREADS) {
      unsigned long long kk = skey[i];
      if (i < n) { sval[i] = inv_orderable((unsigned)(kk >> 32)); sidx[i] = (int)(kk & 0xFFFFFFFFu); }
      else       { sval[i] = -INFINITY; sidx[i] = 0x7FFFFFFF; }
    }
    __syncthreads();
    if (tid == 0) s_ok = (sval[TOPK - 1] > THY) ? 1 : 0;   // proves candidate set covers top-k + ties
  } else {
    if (tid == 0) s_ok = 0;
  }
  __syncthreads();

  // ---- Guarded slow path (full histogram select; bit-identical math). Never taken on
  //      typical data; present so correctness never rests on the prefilter. ----
  if (!s_ok) {
    for (int i = tid; i < NBINS; i += NTHREADS) hist[i] = 0u;
    if (tid == 0) s_cnt = 0u;
    __syncthreads();
    for (int c = tid; c < NV4; c += NTHREADS) {
      float4 t = row4[c];
      int vb = c * 4;
      float xs4[4] = {t.x, t.y, t.z, t.w};
#pragma unroll
      for (int q = 0; q < 4; q++) {
        unsigned e = g_table[vb + q];
        atomicAdd(&hist[orderable(adjust_logit(xs4[q], e)) >> 19], 1u);
      }
    }
    __syncthreads();
    unsigned ps = 0u;
#pragma unroll
    for (int q = 0; q < 8; q++) ps += hist[tid * 8 + q];
    partial[tid] = ps;
    __syncthreads();
    for (int off = 1; off < NTHREADS; off <<= 1) {
      unsigned a = (tid + off < NTHREADS) ? partial[tid + off] : 0u;
      __syncthreads();
      partial[tid] += a;
      __syncthreads();
    }
    {
      unsigned sufi = partial[tid];
      unsigned sufn = (tid + 1 < NTHREADS) ? partial[tid + 1] : 0u;
      if (sufi >= TOPK && sufn < TOPK) s_g = tid;
    }
    __syncthreads();
    if (tid == 0) {
      int g = s_g;
      unsigned acc = (g + 1 < NTHREADS) ? partial[g + 1] : 0u;
      int b = g * 8;
      for (int q = 7; q >= 0; q--) {
        acc += hist[g * 8 + q];
        if (acc >= TOPK) { b = g * 8 + q; break; }
      }
      s_bstar = b;
    }
    __syncthreads();
    const unsigned bstar = (unsigned)s_bstar;
    for (int c = tid; c < NV4; c += NTHREADS) {
      float4 t = row4[c];
      int vb = c * 4;
      float xs4[4] = {t.x, t.y, t.z, t.w};
#pragma unroll
      for (int q = 0; q < 4; q++) {
        unsigned e = g_table[vb + q];
        unsigned o = orderable(adjust_logit(xs4[q], e));
        if ((o >> 19) >= bstar) {
          unsigned p = atomicAdd(&s_cnt, 1u);
          if (p < CAP) skey[p] = ((unsigned long long)o << 32) | (unsigned)(vb + q);
        }
      }
    }
    __syncthreads();
    n = (int)s_cnt; if (n > CAP) n = CAP;
    for (int i = tid; i < CAP; i += NTHREADS)
      if (i >= n) skey[i] = 0ull;
    __syncthreads();
    bitonic_desc(skey, tid);
    for (int i = tid; i < CAP; i += NTHREADS) {
      unsigned long long kk = skey[i];
      if (i < n) { sval[i] = inv_orderable((unsigned)(kk >> 32)); sidx[i] = (int)(kk & 0xFFFFFFFFu); }
      else       { sval[i] = -INFINITY; sidx[i] = 0x7FFFFFFF; }
    }
    __syncthreads();
  }

  // ---- Serial epilogue: tau, softmax, ascending cumsum top-p, renormalize ----
  if (tid == 0) {
    const float T = (float)(1.0 - 0.9);
    float tau = sval[TOPK - 1];
    int Kp = n;
    for (int i = TOPK; i < n; i++) if (sval[i] < tau) { Kp = i; break; }
    float m = sval[0];
    float Ssum = 0.f;
    for (int i = Kp - 1; i >= 0; i--) Ssum += expf(sval[i] - m);   // ascending order
    float c = 0.f; int J = Kp;
    for (int i = Kp - 1; i >= 0; i--) {
      c += expf(sval[i] - m) / Ssum;
      if (c > T) { J = i + 1; break; }
    }
    float Z = 0.f;
    for (int i = J - 1; i >= 0; i--) Z += expf(sval[i] - m);
    for (int i = 0; i < J; i++) sval[i] = expf(sval[i] - m) / Z;
    s_J = J;
  }
  __syncthreads();
  int J = s_J;

  if (prob_off >= 0) {
    float* prow = out + prob_off + (size_t)s * VOCAB;
    for (int i = tid; i < J; i += NTHREADS) prow[sidx[i]] = sval[i];
  }

  // ---- Gumbel-argmax sampling over the J survivors (warp 0) ----
  if (tok_off >= 0 && tid < 32) {
    float best = -INFINITY; int bidx = 0x7FFFFFFF;
    for (int i = tid; i < J; i += 32) {
      float sc = logf(sval[i]) + gumbel_at((long long)s * VOCAB + sidx[i]);
      if (sc > best || (sc == best && sidx[i] < bidx)) { best = sc; bidx = sidx[i]; }
    }
    for (int o = 16; o; o >>= 1) {
      float ob = __shfl_down_sync(0xffffffffu, best, o);
      int oi   = __shfl_down_sync(0xffffffffu, bidx, o);
      if (ob > best || (ob == best && oi < bidx)) { best = ob; bidx = oi; }
    }
    if (tid == 0) {
      if (tok_int) ((int*)out)[tok_off + s] = bidx;
      else         out[tok_off + s] = (float)bidx;
    }
  }
}

extern "C" void kernel_launch(void* const* d_in, const int* in_sizes, int n_in,
                              void* d_out, int out_size) {
  const float* logits = (const float*)d_in[0];
  const int* prompt  = (const int*)d_in[1];
  const int* outtok  = (const int*)d_in[2];
  const int* eos     = (const int*)d_in[3];
  int np = in_sizes[1], no = in_sizes[2], ne = in_sizes[3];

  k_zero_table<<<(VOCAB + 1023) / 1024, 1024>>>();
  k_scatter<<<1, 1024>>>(prompt, np, outtok, no, eos, ne);

  const long long SV = (long long)NSEQ * VOCAB;
  int prob_off, tok_off, tok_int;
  if (out_size == (int)(SV + NSEQ)) { tok_off = 0;  prob_off = NSEQ; tok_int = 0; }
  else if (out_size == (int)SV)     { tok_off = -1; prob_off = 0;    tok_int = 0; }
  else if (out_size == NSEQ)        { tok_off = 0;  prob_off = -1;   tok_int = 1; }
  else                              { tok_off = 0;  prob_off = NSEQ; tok_int = 0; }

  k_main<<<NSEQ, NTHREADS>>>(logits, (float*)d_out, prob_off, tok_off, tok_int);
}

// round 8
// speedup vs baseline: 2.1499x; 1.0067x over previous
#include <cuda_runtime.h>
#include <math.h>
#include <stdint.h>

#define VOCAB    128000
#define NSEQ     256
#define TOPK     50
#define NTHREADS 1024
#define NBINS    8192
#define CAP      512           // candidate capacity == sort size
#define NV4      (VOCAB / 4)
#define THX      2.85f         // raw-logit prefilter
#define THY      3.5625f       // = THX/0.8 : upper bound on y for filtered elements

// per-vocab penalty table: bits[0:16)=output count, bit16=prompt flag, bit17=eos flag
__device__ unsigned g_table[VOCAB];

// One launch: zero the table, then scatter the penalty bits.
__global__ void k_setup(const int* __restrict__ prompt, int np,
                        const int* __restrict__ outtok, int no,
                        const int* __restrict__ eos, int ne) {
  int tid = threadIdx.x;
  uint4* t4 = (uint4*)g_table;
  for (int i = tid; i < VOCAB / 4; i += blockDim.x)
    t4[i] = make_uint4(0u, 0u, 0u, 0u);
  __syncthreads();
  for (int i = tid; i < np; i += blockDim.x) atomicOr(&g_table[prompt[i]], 1u << 16);
  for (int i = tid; i < no; i += blockDim.x) atomicAdd(&g_table[outtok[i]], 1u);
  for (int i = tid; i < ne; i += blockDim.x) atomicOr(&g_table[eos[i]], 1u << 17);
}

// Bit-faithful to the reference float path: every op rounded separately (no FFMA).
__device__ __forceinline__ float adjust_logit(float x, unsigned e) {
  if (e & (1u << 17)) return -INFINITY;                    // eos mask
  int cnt = (int)(e & 0xFFFFu);
  float rep = (e & 0x1FFFFu) ? 1.1f : 1.0f;                // prompt|output mask
  float y = (x > 0.0f) ? __fdiv_rn(x, rep) : __fmul_rn(x, rep);
  y = __fsub_rn(y, __fmul_rn(0.1f, (float)cnt));           // frequency
  if (cnt > 0) y = __fsub_rn(y, 0.2f);                     // presence
  y = __fdiv_rn(y, 0.8f);                                  // temperature
  return y;
}

__device__ __forceinline__ unsigned orderable(float f) {
  unsigned u = __float_as_uint(f);
  return (u & 0x80000000u) ? ~u : (u | 0x80000000u);
}
__device__ __forceinline__ float inv_orderable(unsigned o) {
  return __uint_as_float((o & 0x80000000u) ? (o ^ 0x80000000u) : ~o);
}

// JAX threefry2x32, partitionable: bits = x0 ^ x1 of threefry(key=(0,1), counter=(0, n))
__device__ __forceinline__ float gumbel_at(long long n) {
  unsigned c0 = (unsigned)((unsigned long long)n >> 32);
  unsigned c1 = (unsigned)n;
  const unsigned ks0 = 0u, ks1 = 1u, ks2 = 0x1BD11BDBu;
  unsigned x0 = c0 + ks0, x1 = c1 + ks1;
#define TF_RND(r) { x0 += x1; x1 = (x1 << (r)) | (x1 >> (32 - (r))); x1 ^= x0; }
  TF_RND(13) TF_RND(15) TF_RND(26) TF_RND(6)  x0 += ks1; x1 += ks2 + 1u;
  TF_RND(17) TF_RND(29) TF_RND(16) TF_RND(24) x0 += ks2; x1 += ks0 + 2u;
  TF_RND(13) TF_RND(15) TF_RND(26) TF_RND(6)  x0 += ks0; x1 += ks1 + 3u;
  TF_RND(17) TF_RND(29) TF_RND(16) TF_RND(24) x0 += ks1; x1 += ks2 + 4u;
  TF_RND(13) TF_RND(15) TF_RND(26) TF_RND(6)  x0 += ks2; x1 += ks0 + 5u;
#undef TF_RND
  unsigned bits = x0 ^ x1;
  float f = __uint_as_float((bits >> 9) | 0x3f800000u) - 1.0f;
  float u = fmaxf(__uint_as_float(0x00800000u), f);
  return -logf(-logf(u));
}

// Descending bitonic sort over CAP slots (threads with tid < CAP participate).
__device__ __forceinline__ void bitonic_desc(unsigned long long* skey, int tid) {
  for (int k = 2; k <= CAP; k <<= 1) {
    for (int j = k >> 1; j > 0; j >>= 1) {
      if (tid < CAP) {
        int i = tid, l = i ^ j;
        if (l > i) {
          unsigned long long a = skey[i], b = skey[l];
          bool sw = ((i & k) == 0) ? (a < b) : (a > b);
          if (sw) { skey[i] = b; skey[l] = a; }
        }
      }
      __syncthreads();
    }
  }
}

__global__ __launch_bounds__(NTHREADS, 2)
void k_main(const float* __restrict__ logits, float* __restrict__ out,
            int prob_off, int tok_off, int tok_int) {
  __shared__ unsigned hist[NBINS];          // slow path only
  __shared__ unsigned partial[NTHREADS];    // slow path only
  __shared__ unsigned long long skey[CAP];  // (orderable(y)<<32) | vocab_idx
  __shared__ float sval[CAP];
  __shared__ int   sidx[CAP];
  __shared__ unsigned s_cnt;
  __shared__ int s_g, s_bstar, s_J, s_ok;

  const int s = blockIdx.x;
  const int tid = threadIdx.x;

  if (tid == 0) { s_cnt = 0u; s_g = 0; }
  __syncthreads();

  const float4* row4 = (const float4*)(logits + (size_t)s * VOCAB);
  float4* prow4 = (prob_off >= 0) ? (float4*)(out + prob_off + (size_t)s * VOCAB) : (float4*)0;
  const float4 zero4 = make_float4(0.f, 0.f, 0.f, 0.f);

  // ---- Single streaming pass: fused zero-fill + prefiltered candidate collection ----
  // x <= THX  =>  y <= THY < tau  =>  cannot reach top-k (verified below; slow path otherwise).
#pragma unroll 4
  for (int c = tid; c < NV4; c += NTHREADS) {
    float4 t = __ldcs(&row4[c]);
    if (prow4) __stcs(&prow4[c], zero4);
    float mx = fmaxf(fmaxf(t.x, t.y), fmaxf(t.z, t.w));
    if (mx > THX) {
      int vb = c * 4;
      float xs4[4] = {t.x, t.y, t.z, t.w};
#pragma unroll
      for (int q = 0; q < 4; q++) {
        if (xs4[q] > THX) {
          unsigned e = g_table[vb + q];
          unsigned o = orderable(adjust_logit(xs4[q], e));
          unsigned p = atomicAdd(&s_cnt, 1u);
          if (p < CAP) skey[p] = ((unsigned long long)o << 32) | (unsigned)(vb + q);
        }
      }
    }
  }
  __syncthreads();

  int n = (int)s_cnt;
  bool okn = (n >= TOPK && n <= CAP);
  if (okn) {
    if (tid < CAP && tid >= n) skey[tid] = 0ull;
    __syncthreads();
    bitonic_desc(skey, tid);                 // desc (value, idx): stable-tie reverse of asc argsort
    if (tid < CAP) {
      unsigned long long kk = skey[tid];
      if (tid < n) { sval[tid] = inv_orderable((unsigned)(kk >> 32)); sidx[tid] = (int)(kk & 0xFFFFFFFFu); }
      else         { sval[tid] = -INFINITY; sidx[tid] = 0x7FFFFFFF; }
    }
    __syncthreads();
    if (tid == 0) s_ok = (sval[TOPK - 1] > THY) ? 1 : 0;   // candidate set provably covers top-k + ties
  } else {
    if (tid == 0) s_ok = 0;
  }
  __syncthreads();

  // ---- Guarded slow path (full histogram select; bit-identical math). ----
  if (!s_ok) {
    for (int i = tid; i < NBINS; i += NTHREADS) hist[i] = 0u;
    if (tid == 0) s_cnt = 0u;
    __syncthreads();
    for (int c = tid; c < NV4; c += NTHREADS) {
      float4 t = row4[c];
      int vb = c * 4;
      float xs4[4] = {t.x, t.y, t.z, t.w};
#pragma unroll
      for (int q = 0; q < 4; q++) {
        unsigned e = g_table[vb + q];
        atomicAdd(&hist[orderable(adjust_logit(xs4[q], e)) >> 19], 1u);
      }
    }
    __syncthreads();
    unsigned ps = 0u;
#pragma unroll
    for (int q = 0; q < 8; q++) ps += hist[tid * 8 + q];
    partial[tid] = ps;
    __syncthreads();
    for (int off = 1; off < NTHREADS; off <<= 1) {
      unsigned a = (tid + off < NTHREADS) ? partial[tid + off] : 0u;
      __syncthreads();
      partial[tid] += a;
      __syncthreads();
    }
    {
      unsigned sufi = partial[tid];
      unsigned sufn = (tid + 1 < NTHREADS) ? partial[tid + 1] : 0u;
      if (sufi >= TOPK && sufn < TOPK) s_g = tid;
    }
    __syncthreads();
    if (tid == 0) {
      int g = s_g;
      unsigned acc = (g + 1 < NTHREADS) ? partial[g + 1] : 0u;
      int b = g * 8;
      for (int q = 7; q >= 0; q--) {
        acc += hist[g * 8 + q];
        if (acc >= TOPK) { b = g * 8 + q; break; }
      }
      s_bstar = b;
    }
    __syncthreads();
    const unsigned bstar = (unsigned)s_bstar;
    for (int c = tid; c < NV4; c += NTHREADS) {
      float4 t = row4[c];
      int vb = c * 4;
      float xs4[4] = {t.x, t.y, t.z, t.w};
#pragma unroll
      for (int q = 0; q < 4; q++) {
        unsigned e = g_table[vb + q];
        unsigned o = orderable(adjust_logit(xs4[q], e));
        if ((o >> 19) >= bstar) {
          unsigned p = atomicAdd(&s_cnt, 1u);
          if (p < CAP) skey[p] = ((unsigned long long)o << 32) | (unsigned)(vb + q);
        }
      }
    }
    __syncthreads();
    n = (int)s_cnt; if (n > CAP) n = CAP;
    if (tid < CAP && tid >= n) skey[tid] = 0ull;
    __syncthreads();
    bitonic_desc(skey, tid);
    if (tid < CAP) {
      unsigned long long kk = skey[tid];
      if (tid < n) { sval[tid] = inv_orderable((unsigned)(kk >> 32)); sidx[tid] = (int)(kk & 0xFFFFFFFFu); }
      else         { sval[tid] = -INFINITY; sidx[tid] = 0x7FFFFFFF; }
    }
    __syncthreads();
  }

  // ---- Serial epilogue: tau, softmax, ascending cumsum top-p, renormalize ----
  if (tid == 0) {
    const float T = (float)(1.0 - 0.9);
    float tau = sval[TOPK - 1];
    int Kp = n;
    for (int i = TOPK; i < n; i++) if (sval[i] < tau) { Kp = i; break; }
    float m = sval[0];
    float Ssum = 0.f;
    for (int i = Kp - 1; i >= 0; i--) Ssum += expf(sval[i] - m);   // ascending order
    float c = 0.f; int J = Kp;
    for (int i = Kp - 1; i >= 0; i--) {
      c += expf(sval[i] - m) / Ssum;
      if (c > T) { J = i + 1; break; }
    }
    float Z = 0.f;
    for (int i = J - 1; i >= 0; i--) Z += expf(sval[i] - m);
    for (int i = 0; i < J; i++) sval[i] = expf(sval[i] - m) / Z;
    s_J = J;
  }
  __syncthreads();
  int J = s_J;

  if (prob_off >= 0) {
    float* prow = out + prob_off + (size_t)s * VOCAB;
    for (int i = tid; i < J; i += NTHREADS) prow[sidx[i]] = sval[i];
  }

  // ---- Gumbel-argmax sampling over the J survivors (warp 0) ----
  if (tok_off >= 0 && tid < 32) {
    float best = -INFINITY; int bidx = 0x7FFFFFFF;
    for (int i = tid; i < J; i += 32) {
      float sc = logf(sval[i]) + gumbel_at((long long)s * VOCAB + sidx[i]);
      if (sc > best || (sc == best && sidx[i] < bidx)) { best = sc; bidx = sidx[i]; }
    }
    for (int o = 16; o; o >>= 1) {
      float ob = __shfl_down_sync(0xffffffffu, best, o);
      int oi   = __shfl_down_sync(0xffffffffu, bidx, o);
      if (ob > best || (ob == best && oi < bidx)) { best = ob; bidx = oi; }
    }
    if (tid == 0) {
      if (tok_int) ((int*)out)[tok_off + s] = bidx;
      else         out[tok_off + s] = (float)bidx;
    }
  }
}

extern "C" void kernel_launch(void* const* d_in, const int* in_sizes, int n_in,
                              void* d_out, int out_size) {
  const float* logits = (const float*)d_in[0];
  const int* prompt  = (const int*)d_in[1];
  const int* outtok  = (const int*)d_in[2];
  const int* eos     = (const int*)d_in[3];
  int np = in_sizes[1], no = in_sizes[2], ne = in_sizes[3];

  k_setup<<<1, 1024>>>(prompt, np, outtok, no, eos, ne);

  const long long SV = (long long)NSEQ * VOCAB;
  int prob_off, tok_off, tok_int;
  if (out_size == (int)(SV + NSEQ)) { tok_off = 0;  prob_off = NSEQ; tok_int = 0; }
  else if (out_size == (int)SV)     { tok_off = -1; prob_off = 0;    tok_int = 0; }
  else if (out_size == NSEQ)        { tok_off = 0;  prob_off = -1;   tok_int = 1; }
  else                              { tok_off = 0;  prob_off = NSEQ; tok_int = 0; }

  k_main<<<NSEQ, NTHREADS>>>(logits, (float*)d_out, prob_off, tok_off, tok_int);
}

// round 9
// speedup vs baseline: 2.7626x; 1.2850x over previous
#include <cuda_runtime.h>
#include <math.h>
#include <stdint.h>

#define VOCAB    128000
#define NSEQ     256
#define TOPK     50
#define NTHREADS 1024
#define NBINS    2048          // slow path only (11-bit orderable)
#define CAP      512           // candidate capacity == sort size
#define NV4      (VOCAB / 4)
#define THX      2.85f         // raw-logit prefilter
#define THY      3.5625f       // = THX/0.8 : upper bound on y for filtered elements
#define HSIZE    4096
#define HMASK    4095
#define HEMPTY   0xFFFFFFFFu

// smem hash slot: [id:17][eos:1][prompt:1][cnt:13]
__device__ __forceinline__ void hinsert(unsigned* h, unsigned id, unsigned addv, unsigned orv) {
  unsigned slot = (id * 2654435761u) >> 20;
  unsigned tag = id << 15;
  for (;;) {
    unsigned cur = h[slot];
    if (cur == HEMPTY) {
      unsigned prev = atomicCAS(&h[slot], HEMPTY, tag);
      cur = (prev == HEMPTY) ? tag : prev;
    }
    if ((cur >> 15) == id) {
      if (orv)  atomicOr(&h[slot], orv);
      if (addv) atomicAdd(&h[slot], addv);
      return;
    }
    slot = (slot + 1) & HMASK;
  }
}
__device__ __forceinline__ unsigned hlookup(const unsigned* h, unsigned id) {
  unsigned slot = (id * 2654435761u) >> 20;
  for (;;) {
    unsigned cur = h[slot];
    if (cur == HEMPTY) return 0u;
    if ((cur >> 15) == id) return cur;
    slot = (slot + 1) & HMASK;
  }
}

// Bit-faithful to the reference float path: every op rounded separately (no FFMA).
__device__ __forceinline__ float adjust_logit(float x, unsigned cur) {
  if (cur & (1u << 14)) return -INFINITY;                  // eos mask
  unsigned cnt = cur & 0x1FFFu;
  bool penal = (cur & (1u << 13)) || (cnt != 0);           // prompt|output mask
  float rep = penal ? 1.1f : 1.0f;
  float y = (x > 0.0f) ? __fdiv_rn(x, rep) : __fmul_rn(x, rep);
  y = __fsub_rn(y, __fmul_rn(0.1f, (float)cnt));           // frequency
  if (cnt > 0) y = __fsub_rn(y, 0.2f);                     // presence
  y = __fdiv_rn(y, 0.8f);                                  // temperature
  return y;
}

__device__ __forceinline__ unsigned orderable(float f) {
  unsigned u = __float_as_uint(f);
  return (u & 0x80000000u) ? ~u : (u | 0x80000000u);
}
__device__ __forceinline__ float inv_orderable(unsigned o) {
  return __uint_as_float((o & 0x80000000u) ? (o ^ 0x80000000u) : ~o);
}

// JAX threefry2x32, partitionable: bits = x0 ^ x1 of threefry(key=(0,1), counter=(0, n))
__device__ __forceinline__ float gumbel_at(long long n) {
  unsigned c0 = (unsigned)((unsigned long long)n >> 32);
  unsigned c1 = (unsigned)n;
  const unsigned ks0 = 0u, ks1 = 1u, ks2 = 0x1BD11BDBu;
  unsigned x0 = c0 + ks0, x1 = c1 + ks1;
#define TF_RND(r) { x0 += x1; x1 = (x1 << (r)) | (x1 >> (32 - (r))); x1 ^= x0; }
  TF_RND(13) TF_RND(15) TF_RND(26) TF_RND(6)  x0 += ks1; x1 += ks2 + 1u;
  TF_RND(17) TF_RND(29) TF_RND(16) TF_RND(24) x0 += ks2; x1 += ks0 + 2u;
  TF_RND(13) TF_RND(15) TF_RND(26) TF_RND(6)  x0 += ks0; x1 += ks1 + 3u;
  TF_RND(17) TF_RND(29) TF_RND(16) TF_RND(24) x0 += ks1; x1 += ks2 + 4u;
  TF_RND(13) TF_RND(15) TF_RND(26) TF_RND(6)  x0 += ks2; x1 += ks0 + 5u;
#undef TF_RND
  unsigned bits = x0 ^ x1;
  float f = __uint_as_float((bits >> 9) | 0x3f800000u) - 1.0f;
  float u = fmaxf(__uint_as_float(0x00800000u), f);
  return -logf(-logf(u));
}

#define BAR512() asm volatile("bar.sync 1, 512;" ::: "memory")

// Descending bitonic sort of 512 u64 keys, one per thread (tid<512 call this).
// shfl for strides <32; double-buffered smem + named barrier for strides >=32.
__device__ __forceinline__ unsigned long long sort512(
    unsigned long long e, unsigned long long* bufA, unsigned long long* bufB, int tid) {
  int phase = 0;
#pragma unroll
  for (int k = 2; k <= 512; k <<= 1) {
#pragma unroll
    for (int j = k >> 1; j > 0; j >>= 1) {
      unsigned long long o;
      if (j < 32) {
        o = __shfl_xor_sync(0xffffffffu, e, j);
      } else {
        unsigned long long* buf = (phase & 1) ? bufB : bufA;
        buf[tid] = e;
        BAR512();
        o = buf[tid ^ j];
        phase ^= 1;
      }
      bool dirAsc = ((tid & k) != 0);       // final pass: all descending
      bool lower  = ((tid & j) == 0);
      bool takeMin = (dirAsc == lower);
      if (takeMin ? (o < e) : (o > e)) e = o;
    }
  }
  BAR512();          // all cross-warp reads done before writeback
  bufA[tid] = e;
  return e;
}

__global__ __launch_bounds__(NTHREADS, 2)
void k_main(const float* __restrict__ logits,
            const int* __restrict__ prompt, int np,
            const int* __restrict__ outtok, int no,
            const int* __restrict__ eos, int ne,
            float* __restrict__ out,
            int prob_off, int tok_off, int tok_int) {
  __shared__ unsigned s_hash[HSIZE];                     // 16 KB
  __shared__ __align__(16) unsigned long long bufA[CAP]; // 4 KB (candidates / sort buf)
  __shared__ __align__(16) unsigned long long u64mem[1024]; // 8 KB union: bufB|sval|sidx OR hist
  __shared__ float se[CAP];                              // 2 KB
  __shared__ unsigned partial[NTHREADS];                 // 4 KB (slow path scan)
  __shared__ unsigned s_cnt;
  __shared__ int s_g, s_bstar, s_J, s_ok, s_n;
  __shared__ float s_Z;

  unsigned long long* bufB = u64mem;                 // 4 KB
  float* sval = (float*)(u64mem + 512);              // 2 KB
  int*   sidx = (int*)((char*)(u64mem + 512) + 2048);// 2 KB
  unsigned* hist = (unsigned*)u64mem;                // 8 KB (slow path, unions all of bufB/sval/sidx)

  const int s = blockIdx.x;
  const int tid = threadIdx.x;

  // ---- Per-CTA penalty hash build (replaces global table + setup kernel) ----
  for (int i = tid; i < HSIZE; i += NTHREADS) s_hash[i] = HEMPTY;
  if (tid == 0) { s_cnt = 0u; s_g = 0; }
  __syncthreads();
  for (int i = tid; i < np; i += NTHREADS) hinsert(s_hash, (unsigned)prompt[i], 0u, 1u << 13);
  for (int i = tid; i < no; i += NTHREADS) hinsert(s_hash, (unsigned)outtok[i], 1u, 0u);
  for (int i = tid; i < ne; i += NTHREADS) hinsert(s_hash, (unsigned)eos[i], 0u, 1u << 14);
  __syncthreads();

  const float4* row4 = (const float4*)(logits + (size_t)s * VOCAB);
  float4* prow4 = (prob_off >= 0) ? (float4*)(out + prob_off + (size_t)s * VOCAB) : (float4*)0;
  const float4 zero4 = make_float4(0.f, 0.f, 0.f, 0.f);

  // ---- Single streaming pass: fused zero-fill + prefiltered candidate collection ----
#pragma unroll 4
  for (int c = tid; c < NV4; c += NTHREADS) {
    float4 t = __ldcs(&row4[c]);
    if (prow4) __stcs(&prow4[c], zero4);
    float mx = fmaxf(fmaxf(t.x, t.y), fmaxf(t.z, t.w));
    if (mx > THX) {
      int vb = c * 4;
      float xs4[4] = {t.x, t.y, t.z, t.w};
#pragma unroll
      for (int q = 0; q < 4; q++) {
        if (xs4[q] > THX) {
          unsigned cur = hlookup(s_hash, (unsigned)(vb + q));
          unsigned o = orderable(adjust_logit(xs4[q], cur));
          unsigned p = atomicAdd(&s_cnt, 1u);
          if (p < CAP) bufA[p] = ((unsigned long long)o << 32) | (unsigned)(vb + q);
        }
      }
    }
  }
  __syncthreads();

  int n = (int)s_cnt;
  bool okn = (n >= TOPK && n <= CAP);
  if (okn) {
    if (tid < CAP) {
      unsigned long long e = (tid < n) ? bufA[tid] : 0ull;
      sort512(e, bufA, bufB, tid);
    }
    __syncthreads();
    if (tid == 0) {
      float v50 = inv_orderable((unsigned)(bufA[TOPK - 1] >> 32));
      s_ok = (v50 > THY) ? 1 : 0;     // candidate set provably covers top-k + ties
      s_n = n;
    }
  } else {
    if (tid == 0) s_ok = 0;
  }
  __syncthreads();

  // ---- Guarded slow path (histogram select over full vocab; bit-identical math) ----
  if (!s_ok) {
    for (int i = tid; i < NBINS; i += NTHREADS) hist[i] = 0u;
    if (tid == 0) s_cnt = 0u;
    __syncthreads();
    for (int c = tid; c < NV4; c += NTHREADS) {
      float4 t = row4[c];
      int vb = c * 4;
      float xs4[4] = {t.x, t.y, t.z, t.w};
#pragma unroll
      for (int q = 0; q < 4; q++) {
        unsigned cur = hlookup(s_hash, (unsigned)(vb + q));
        atomicAdd(&hist[orderable(adjust_logit(xs4[q], cur)) >> 21], 1u);
      }
    }
    __syncthreads();
    unsigned ps = hist[2 * tid] + hist[2 * tid + 1];
    partial[tid] = ps;
    __syncthreads();
    for (int off = 1; off < NTHREADS; off <<= 1) {
      unsigned a = (tid + off < NTHREADS) ? partial[tid + off] : 0u;
      __syncthreads();
      partial[tid] += a;
      __syncthreads();
    }
    {
      unsigned sufi = partial[tid];
      unsigned sufn = (tid + 1 < NTHREADS) ? partial[tid + 1] : 0u;
      if (sufi >= TOPK && sufn < TOPK) s_g = tid;
    }
    __syncthreads();
    if (tid == 0) {
      int g = s_g;
      unsigned acc = (g + 1 < NTHREADS) ? partial[g + 1] : 0u;
      int b = 2 * g;
      for (int q = 1; q >= 0; q--) {
        acc += hist[2 * g + q];
        if (acc >= TOPK) { b = 2 * g + q; break; }
      }
      s_bstar = b;
    }
    __syncthreads();
    const unsigned bstar = (unsigned)s_bstar;
    // hist is dead from here; bufA collection may alias freely
    if (tid == 0) s_cnt = 0u;
    __syncthreads();
    for (int c = tid; c < NV4; c += NTHREADS) {
      float4 t = row4[c];
      int vb = c * 4;
      float xs4[4] = {t.x, t.y, t.z, t.w};
#pragma unroll
      for (int q = 0; q < 4; q++) {
        unsigned cur = hlookup(s_hash, (unsigned)(vb + q));
        unsigned o = orderable(adjust_logit(xs4[q], cur));
        if ((o >> 21) >= bstar) {
          unsigned p = atomicAdd(&s_cnt, 1u);
          if (p < CAP) bufA[p] = ((unsigned long long)o << 32) | (unsigned)(vb + q);
        }
      }
    }
    __syncthreads();
    if (tid == 0) { int m = (int)s_cnt; s_n = (m > CAP) ? CAP : m; }
    __syncthreads();
    n = s_n;
    if (tid < CAP) {
      unsigned long long e = (tid < n) ? bufA[tid] : 0ull;
      sort512(e, bufA, bufB, tid);
    }
    __syncthreads();
  }
  n = s_n;

  // ---- Decode + parallel exps ----
  if (tid < CAP) {
    unsigned long long kk = bufA[tid];
    if (tid < n) { sval[tid] = inv_orderable((unsigned)(kk >> 32)); sidx[tid] = (int)(kk & 0xFFFFFFFFu); }
    else         { sval[tid] = -INFINITY; sidx[tid] = 0x7FFFFFFF; }
  }
  __syncthreads();
  float m0 = sval[0];
  if (tid < CAP) se[tid] = (tid < n) ? expf(sval[tid] - m0) : 0.0f;
  __syncthreads();

  // ---- Serial epilogue (order-sensitive sums only) ----
  if (tid == 0) {
    const float T = (float)(1.0 - 0.9);
    float tau = sval[TOPK - 1];
    int Kp = n;
    for (int i = TOPK; i < n; i++) if (sval[i] < tau) { Kp = i; break; }
    float Ssum = 0.f;
    for (int i = Kp - 1; i >= 0; i--) Ssum += se[i];           // ascending value order
    float c = 0.f; int J = Kp;
    for (int i = Kp - 1; i >= 0; i--) {
      c += se[i] / Ssum;
      if (c > T) { J = i + 1; break; }
    }
    float Z = 0.f;
    for (int i = J - 1; i >= 0; i--) Z += se[i];
    s_J = J; s_Z = Z;
  }
  __syncthreads();
  int J = s_J;
  float Z = s_Z;

  if (prob_off >= 0) {
    float* prow = out + prob_off + (size_t)s * VOCAB;
    for (int i = tid; i < J; i += NTHREADS) prow[sidx[i]] = se[i] / Z;
  }

  // ---- Gumbel-argmax sampling over the J survivors (warp 0) ----
  if (tok_off >= 0 && tid < 32) {
    float best = -INFINITY; int bidx = 0x7FFFFFFF;
    for (int i = tid; i < J; i += 32) {
      float sc = logf(se[i] / Z) + gumbel_at((long long)s * VOCAB + sidx[i]);
      if (sc > best || (sc == best && sidx[i] < bidx)) { best = sc; bidx = sidx[i]; }
    }
    for (int o = 16; o; o >>= 1) {
      float ob = __shfl_down_sync(0xffffffffu, best, o);
      int oi   = __shfl_down_sync(0xffffffffu, bidx, o);
      if (ob > best || (ob == best && oi < bidx)) { best = ob; bidx = oi; }
    }
    if (tid == 0) {
      if (tok_int) ((int*)out)[tok_off + s] = bidx;
      else         out[tok_off + s] = (float)bidx;
    }
  }
}

extern "C" void kernel_launch(void* const* d_in, const int* in_sizes, int n_in,
                              void* d_out, int out_size) {
  const float* logits = (const float*)d_in[0];
  const int* prompt  = (const int*)d_in[1];
  const int* outtok  = (const int*)d_in[2];
  const int* eos     = (const int*)d_in[3];
  int np = in_sizes[1], no = in_sizes[2], ne = in_sizes[3];

  const long long SV = (long long)NSEQ * VOCAB;
  int prob_off, tok_off, tok_int;
  if (out_size == (int)(SV + NSEQ)) { tok_off = 0;  prob_off = NSEQ; tok_int = 0; }
  else if (out_size == (int)SV)     { tok_off = -1; prob_off = 0;    tok_int = 0; }
  else if (out_size == NSEQ)        { tok_off = 0;  prob_off = -1;   tok_int = 1; }
  else                              { tok_off = 0;  prob_off = NSEQ; tok_int = 0; }

  k_main<<<NSEQ, NTHREADS>>>(logits, prompt, np, outtok, no, eos, ne,
                             (float*)d_out, prob_off, tok_off, tok_int);
}